// round 2
// baseline (speedup 1.0000x reference)
#include <cuda_runtime.h>
#include <math.h>

#define B_SZ   16384
#define SCENE  256
#define FEAT   256
#define HID    1024
#define NSLOTS 8

// ---------------- scratch (allocation-free: __device__ globals) -------------
__device__ float g_x0[B_SZ * FEAT];   // encoder output (input to step 0)
__device__ float g_hA[B_SZ * HID];    // h ping
__device__ float g_hB[B_SZ * HID];    // h pong
__device__ float g_c [B_SZ * HID];    // cell state (updated in place)

// ---------------- math helpers ----------------------------------------------
__device__ __forceinline__ float sigmoidf_(float x) {
    return 1.0f / (1.0f + expf(-x));
}
__device__ __forceinline__ float softplusf_(float x) {
    return fmaxf(x, 0.0f) + log1pf(expf(-fabsf(x)));
}
__device__ __forceinline__ float gelu_exact_(float x) {
    return 0.5f * x * (1.0f + erff(x * 0.7071067811865476f));
}

// =============================================================================
// Encoder: x0 = gelu(S @ We^T + be)   [B,SCENE] x [FEAT,SCENE]^T -> [B,FEAT]
// =============================================================================
__global__ void __launch_bounds__(256, 2) enc_kernel(
    const float* __restrict__ S, const float* __restrict__ We,
    const float* __restrict__ be)
{
    __shared__ float As[16 * 65];
    __shared__ float Ws[16 * 33];

    const int tid = threadIdx.x;
    const int tx  = tid & 15, ty = tid >> 4;
    const int m0  = blockIdx.x * 64;
    const int n0  = blockIdx.y * 32;

    float acc[8];
#pragma unroll
    for (int i = 0; i < 8; ++i) acc[i] = 0.f;

    const int rowl = tid >> 2;
    const int kcl  = (tid & 3) * 4;

    for (int k0 = 0; k0 < SCENE; k0 += 16) {
        {
            float4 v = *reinterpret_cast<const float4*>(
                &S[(size_t)(m0 + rowl) * SCENE + k0 + kcl]);
            As[(kcl + 0) * 65 + rowl] = v.x; As[(kcl + 1) * 65 + rowl] = v.y;
            As[(kcl + 2) * 65 + rowl] = v.z; As[(kcl + 3) * 65 + rowl] = v.w;
        }
        if (tid < 128) {
            int col = tid >> 2;
            int kc  = (tid & 3) * 4;
            float4 v = *reinterpret_cast<const float4*>(
                &We[(size_t)(n0 + col) * SCENE + k0 + kc]);
            Ws[(kc + 0) * 33 + col] = v.x; Ws[(kc + 1) * 33 + col] = v.y;
            Ws[(kc + 2) * 33 + col] = v.z; Ws[(kc + 3) * 33 + col] = v.w;
        }
        __syncthreads();
#pragma unroll
        for (int k = 0; k < 16; ++k) {
            float a0 = As[k * 65 + ty * 4 + 0];
            float a1 = As[k * 65 + ty * 4 + 1];
            float a2 = As[k * 65 + ty * 4 + 2];
            float a3 = As[k * 65 + ty * 4 + 3];
            float w0 = Ws[k * 33 + tx * 2 + 0];
            float w1 = Ws[k * 33 + tx * 2 + 1];
            acc[0] = fmaf(a0, w0, acc[0]); acc[1] = fmaf(a0, w1, acc[1]);
            acc[2] = fmaf(a1, w0, acc[2]); acc[3] = fmaf(a1, w1, acc[3]);
            acc[4] = fmaf(a2, w0, acc[4]); acc[5] = fmaf(a2, w1, acc[5]);
            acc[6] = fmaf(a3, w0, acc[6]); acc[7] = fmaf(a3, w1, acc[7]);
        }
        __syncthreads();
    }

#pragma unroll
    for (int c = 0; c < 2; ++c) {
        const int col = n0 + tx * 2 + c;
        const float b = be[col];
#pragma unroll
        for (int r = 0; r < 4; ++r) {
            const int row = m0 + ty * 4 + r;
            g_x0[(size_t)row * FEAT + col] = gelu_exact_(acc[r * 2 + c] + b);
        }
    }
}

// =============================================================================
// Gates GEMM + fused LSTM cell.
//   x_t = (t==0 ? x0 : z_{t-1})   <-- autoregressive: sampled z feeds forward
//   gates = x_t @ W_ih^T + h_{t-1} @ W_hh^T + b;  cell update fused in epilogue.
// =============================================================================
template <bool FIRST>
__global__ void __launch_bounds__(256, 2) gates_kernel(
    int t, const float* __restrict__ x,
    const float* __restrict__ W_ih, const float* __restrict__ W_hh,
    const float* __restrict__ b_ih, const float* __restrict__ b_hh)
{
    float*       hout  = (t & 1) ? g_hB : g_hA;
    const float* hprev = (t & 1) ? g_hA : g_hB;

    __shared__ float As[16 * 65];       // [k][row]
    __shared__ float Ws[4 * 16 * 33];   // [gate][k][col]

    const int tid = threadIdx.x;
    const int tx  = tid & 15, ty = tid >> 4;
    const int m0  = blockIdx.x * 64;
    const int n0  = blockIdx.y * 32;

    const int rowl = tid >> 2;
    const int kcl  = (tid & 3) * 4;
    const int q1 = tid,        g1 = q1 >> 7, col1 = (q1 & 127) >> 2, kq1 = (q1 & 3) * 4;
    const int q2 = tid + 256,  g2 = q2 >> 7, col2 = (q2 & 127) >> 2, kq2 = (q2 & 3) * 4;

    const int KT = FIRST ? FEAT : (FEAT + HID);

    float acc[4][8];
#pragma unroll
    for (int g = 0; g < 4; ++g)
#pragma unroll
        for (int i = 0; i < 8; ++i) acc[g][i] = 0.f;

    float4 va, vw1, vw2;
    va  = *reinterpret_cast<const float4*>(&x[(size_t)(m0 + rowl) * FEAT + kcl]);
    vw1 = *reinterpret_cast<const float4*>(&W_ih[(size_t)(g1 * HID + n0 + col1) * FEAT + kq1]);
    vw2 = *reinterpret_cast<const float4*>(&W_ih[(size_t)(g2 * HID + n0 + col2) * FEAT + kq2]);

    for (int kt = 0; kt < KT; kt += 16) {
        As[(kcl + 0) * 65 + rowl] = va.x; As[(kcl + 1) * 65 + rowl] = va.y;
        As[(kcl + 2) * 65 + rowl] = va.z; As[(kcl + 3) * 65 + rowl] = va.w;
        Ws[(g1 * 16 + kq1 + 0) * 33 + col1] = vw1.x;
        Ws[(g1 * 16 + kq1 + 1) * 33 + col1] = vw1.y;
        Ws[(g1 * 16 + kq1 + 2) * 33 + col1] = vw1.z;
        Ws[(g1 * 16 + kq1 + 3) * 33 + col1] = vw1.w;
        Ws[(g2 * 16 + kq2 + 0) * 33 + col2] = vw2.x;
        Ws[(g2 * 16 + kq2 + 1) * 33 + col2] = vw2.y;
        Ws[(g2 * 16 + kq2 + 2) * 33 + col2] = vw2.z;
        Ws[(g2 * 16 + kq2 + 3) * 33 + col2] = vw2.w;
        __syncthreads();

        const int ktn = kt + 16;
        if (ktn < KT) {
            if (ktn < FEAT) {
                va  = *reinterpret_cast<const float4*>(&x[(size_t)(m0 + rowl) * FEAT + ktn + kcl]);
                vw1 = *reinterpret_cast<const float4*>(&W_ih[(size_t)(g1 * HID + n0 + col1) * FEAT + ktn + kq1]);
                vw2 = *reinterpret_cast<const float4*>(&W_ih[(size_t)(g2 * HID + n0 + col2) * FEAT + ktn + kq2]);
            } else {
                const int k0 = ktn - FEAT;
                va  = *reinterpret_cast<const float4*>(&hprev[(size_t)(m0 + rowl) * HID + k0 + kcl]);
                vw1 = *reinterpret_cast<const float4*>(&W_hh[(size_t)(g1 * HID + n0 + col1) * HID + k0 + kq1]);
                vw2 = *reinterpret_cast<const float4*>(&W_hh[(size_t)(g2 * HID + n0 + col2) * HID + k0 + kq2]);
            }
        }

#pragma unroll
        for (int k = 0; k < 16; ++k) {
            const float a0 = As[k * 65 + ty * 4 + 0];
            const float a1 = As[k * 65 + ty * 4 + 1];
            const float a2 = As[k * 65 + ty * 4 + 2];
            const float a3 = As[k * 65 + ty * 4 + 3];
#pragma unroll
            for (int g = 0; g < 4; ++g) {
                const float w0 = Ws[(g * 16 + k) * 33 + tx * 2 + 0];
                const float w1 = Ws[(g * 16 + k) * 33 + tx * 2 + 1];
                acc[g][0] = fmaf(a0, w0, acc[g][0]); acc[g][1] = fmaf(a0, w1, acc[g][1]);
                acc[g][2] = fmaf(a1, w0, acc[g][2]); acc[g][3] = fmaf(a1, w1, acc[g][3]);
                acc[g][4] = fmaf(a2, w0, acc[g][4]); acc[g][5] = fmaf(a2, w1, acc[g][5]);
                acc[g][6] = fmaf(a3, w0, acc[g][6]); acc[g][7] = fmaf(a3, w1, acc[g][7]);
            }
        }
        __syncthreads();
    }

#pragma unroll
    for (int c = 0; c < 2; ++c) {
        const int col = n0 + tx * 2 + c;
        const float bi = b_ih[col]           + b_hh[col];
        const float bf = b_ih[HID + col]     + b_hh[HID + col];
        const float bg = b_ih[2 * HID + col] + b_hh[2 * HID + col];
        const float bo = b_ih[3 * HID + col] + b_hh[3 * HID + col];
#pragma unroll
        for (int r = 0; r < 4; ++r) {
            const int row = m0 + ty * 4 + r;
            const size_t idx = (size_t)row * HID + col;
            const float gi = acc[0][r * 2 + c] + bi;
            const float gf = acc[1][r * 2 + c] + bf;
            const float gg = acc[2][r * 2 + c] + bg;
            const float go = acc[3][r * 2 + c] + bo;
            const float cprev = FIRST ? 0.f : g_c[idx];
            const float cn = sigmoidf_(gf) * cprev + sigmoidf_(gi) * tanhf(gg);
            g_c[idx]  = cn;
            hout[idx] = sigmoidf_(go) * tanhf(cn);
        }
    }
}

// =============================================================================
// Output heads: mu / sigma / z  (z feeds the next step's gates kernel)
// =============================================================================
__global__ void __launch_bounds__(256, 2) out_kernel(
    int t,
    const float* __restrict__ W_mu, const float* __restrict__ W_sp,
    const float* __restrict__ b_mu, const float* __restrict__ b_sp,
    const float* __restrict__ eps,
    float* __restrict__ zs, float* __restrict__ mus, float* __restrict__ sgs)
{
    const float* h = (t & 1) ? g_hB : g_hA;

    __shared__ float As[16 * 65];
    __shared__ float Ws[2 * 16 * 33];

    const int tid = threadIdx.x;
    const int tx  = tid & 15, ty = tid >> 4;
    const int m0  = blockIdx.x * 64;
    const int n0  = blockIdx.y * 32;

    const int rowl = tid >> 2;
    const int kcl  = (tid & 3) * 4;
    const int sw   = tid >> 7;
    const int colw = (tid & 127) >> 2;
    const int kqw  = (tid & 3) * 4;
    const float* Wme = sw ? W_sp : W_mu;

    float acc[2][8];
#pragma unroll
    for (int s = 0; s < 2; ++s)
#pragma unroll
        for (int i = 0; i < 8; ++i) acc[s][i] = 0.f;

    float4 va, vw;
    va = *reinterpret_cast<const float4*>(&h[(size_t)(m0 + rowl) * HID + kcl]);
    vw = *reinterpret_cast<const float4*>(&Wme[(size_t)(n0 + colw) * HID + kqw]);

    for (int k0 = 0; k0 < HID; k0 += 16) {
        As[(kcl + 0) * 65 + rowl] = va.x; As[(kcl + 1) * 65 + rowl] = va.y;
        As[(kcl + 2) * 65 + rowl] = va.z; As[(kcl + 3) * 65 + rowl] = va.w;
        Ws[(sw * 16 + kqw + 0) * 33 + colw] = vw.x;
        Ws[(sw * 16 + kqw + 1) * 33 + colw] = vw.y;
        Ws[(sw * 16 + kqw + 2) * 33 + colw] = vw.z;
        Ws[(sw * 16 + kqw + 3) * 33 + colw] = vw.w;
        __syncthreads();

        const int kn = k0 + 16;
        if (kn < HID) {
            va = *reinterpret_cast<const float4*>(&h[(size_t)(m0 + rowl) * HID + kn + kcl]);
            vw = *reinterpret_cast<const float4*>(&Wme[(size_t)(n0 + colw) * HID + kn + kqw]);
        }

#pragma unroll
        for (int k = 0; k < 16; ++k) {
            const float a0 = As[k * 65 + ty * 4 + 0];
            const float a1 = As[k * 65 + ty * 4 + 1];
            const float a2 = As[k * 65 + ty * 4 + 2];
            const float a3 = As[k * 65 + ty * 4 + 3];
#pragma unroll
            for (int s = 0; s < 2; ++s) {
                const float w0 = Ws[(s * 16 + k) * 33 + tx * 2 + 0];
                const float w1 = Ws[(s * 16 + k) * 33 + tx * 2 + 1];
                acc[s][0] = fmaf(a0, w0, acc[s][0]); acc[s][1] = fmaf(a0, w1, acc[s][1]);
                acc[s][2] = fmaf(a1, w0, acc[s][2]); acc[s][3] = fmaf(a1, w1, acc[s][3]);
                acc[s][4] = fmaf(a2, w0, acc[s][4]); acc[s][5] = fmaf(a2, w1, acc[s][5]);
                acc[s][6] = fmaf(a3, w0, acc[s][6]); acc[s][7] = fmaf(a3, w1, acc[s][7]);
            }
        }
        __syncthreads();
    }

#pragma unroll
    for (int c = 0; c < 2; ++c) {
        const int col = n0 + tx * 2 + c;
        const float bm = b_mu[col];
        const float bs = b_sp[col];
#pragma unroll
        for (int r = 0; r < 4; ++r) {
            const int row = m0 + ty * 4 + r;
            const size_t oidx = (size_t)t * B_SZ * FEAT + (size_t)row * FEAT + col;
            const float mu = acc[0][r * 2 + c] + bm;
            const float sg = softplusf_(acc[1][r * 2 + c] + bs);  // T_TEMP = 1
            zs[oidx]  = mu + sg * eps[oidx];
            mus[oidx] = mu;
            sgs[oidx] = sg;
        }
    }
}

// =============================================================================
// launch
// =============================================================================
extern "C" void kernel_launch(void* const* d_in, const int* in_sizes, int n_in,
                              void* d_out, int out_size)
{
    (void)in_sizes; (void)n_in; (void)out_size;
    const float* S    = (const float*)d_in[0];
    const float* eps  = (const float*)d_in[1];
    // d_in[2] = num_slots (8)
    const float* We   = (const float*)d_in[3];
    const float* be   = (const float*)d_in[4];
    const float* W_ih = (const float*)d_in[5];
    const float* W_hh = (const float*)d_in[6];
    const float* b_ih = (const float*)d_in[7];
    const float* b_hh = (const float*)d_in[8];
    const float* W_mu = (const float*)d_in[9];
    const float* b_mu = (const float*)d_in[10];
    const float* W_sp = (const float*)d_in[11];
    const float* b_sp = (const float*)d_in[12];

    float* out = (float*)d_out;
    const size_t slab = (size_t)NSLOTS * B_SZ * FEAT;
    float* zs  = out;
    float* mus = out + slab;
    float* sgs = out + 2 * slab;

    const dim3 blk(256);
    enc_kernel<<<dim3(B_SZ / 64, FEAT / 32), blk>>>(S, We, be);

    // device-symbol address for g_x0 (host-side &g_x0 is not the device ptr;
    // use cudaGetSymbolAddress once — it's not an allocation)
    static float* x0_ptr = nullptr;
    if (!x0_ptr) cudaGetSymbolAddress((void**)&x0_ptr, g_x0);

    for (int t = 0; t < NSLOTS; ++t) {
        const float* x = (t == 0) ? (const float*)x0_ptr
                                  : zs + (size_t)(t - 1) * B_SZ * FEAT;
        if (t == 0)
            gates_kernel<true><<<dim3(B_SZ / 64, HID / 32), blk>>>(t, x, W_ih, W_hh, b_ih, b_hh);
        else
            gates_kernel<false><<<dim3(B_SZ / 64, HID / 32), blk>>>(t, x, W_ih, W_hh, b_ih, b_hh);

        out_kernel<<<dim3(B_SZ / 64, FEAT / 32), blk>>>(
            t, W_mu, W_sp, b_mu, b_sp, eps, zs, mus, sgs);
    }
}

// round 3
// speedup vs baseline: 1.0012x; 1.0012x over previous
#include <cuda_runtime.h>
#include <math.h>

#define B_SZ   16384
#define SCENE  256
#define FEAT   256
#define HID    1024
#define NSLOTS 8

// ---------------- scratch (allocation-free: __device__ globals) -------------
__device__ float g_x0[B_SZ * FEAT];   // encoder output (input to step 0)
__device__ float g_hA[B_SZ * HID];    // h ping
__device__ float g_hB[B_SZ * HID];    // h pong
__device__ float g_c [B_SZ * HID];    // cell state (updated in place)

// ---------------- math helpers ----------------------------------------------
__device__ __forceinline__ float sigmoidf_(float x) {
    return 1.0f / (1.0f + expf(-x));
}
__device__ __forceinline__ float softplusf_(float x) {
    return fmaxf(x, 0.0f) + log1pf(expf(-fabsf(x)));
}
__device__ __forceinline__ float gelu_exact_(float x) {
    return 0.5f * x * (1.0f + erff(x * 0.7071067811865476f));
}

// =============================================================================
// Encoder: x0 = gelu(S @ We^T + be)   [B,SCENE] x [FEAT,SCENE]^T -> [B,FEAT]
// =============================================================================
__global__ void __launch_bounds__(256, 2) enc_kernel(
    const float* __restrict__ S, const float* __restrict__ We,
    const float* __restrict__ be)
{
    __shared__ float As[16 * 65];
    __shared__ float Ws[16 * 33];

    const int tid = threadIdx.x;
    const int tx  = tid & 15, ty = tid >> 4;
    const int m0  = blockIdx.x * 64;
    const int n0  = blockIdx.y * 32;

    float acc[8];
#pragma unroll
    for (int i = 0; i < 8; ++i) acc[i] = 0.f;

    const int rowl = tid >> 2;
    const int kcl  = (tid & 3) * 4;

    for (int k0 = 0; k0 < SCENE; k0 += 16) {
        {
            float4 v = *reinterpret_cast<const float4*>(
                &S[(size_t)(m0 + rowl) * SCENE + k0 + kcl]);
            As[(kcl + 0) * 65 + rowl] = v.x; As[(kcl + 1) * 65 + rowl] = v.y;
            As[(kcl + 2) * 65 + rowl] = v.z; As[(kcl + 3) * 65 + rowl] = v.w;
        }
        if (tid < 128) {
            int col = tid >> 2;
            int kc  = (tid & 3) * 4;
            float4 v = *reinterpret_cast<const float4*>(
                &We[(size_t)(n0 + col) * SCENE + k0 + kc]);
            Ws[(kc + 0) * 33 + col] = v.x; Ws[(kc + 1) * 33 + col] = v.y;
            Ws[(kc + 2) * 33 + col] = v.z; Ws[(kc + 3) * 33 + col] = v.w;
        }
        __syncthreads();
#pragma unroll
        for (int k = 0; k < 16; ++k) {
            float a0 = As[k * 65 + ty * 4 + 0];
            float a1 = As[k * 65 + ty * 4 + 1];
            float a2 = As[k * 65 + ty * 4 + 2];
            float a3 = As[k * 65 + ty * 4 + 3];
            float w0 = Ws[k * 33 + tx * 2 + 0];
            float w1 = Ws[k * 33 + tx * 2 + 1];
            acc[0] = fmaf(a0, w0, acc[0]); acc[1] = fmaf(a0, w1, acc[1]);
            acc[2] = fmaf(a1, w0, acc[2]); acc[3] = fmaf(a1, w1, acc[3]);
            acc[4] = fmaf(a2, w0, acc[4]); acc[5] = fmaf(a2, w1, acc[5]);
            acc[6] = fmaf(a3, w0, acc[6]); acc[7] = fmaf(a3, w1, acc[7]);
        }
        __syncthreads();
    }

#pragma unroll
    for (int c = 0; c < 2; ++c) {
        const int col = n0 + tx * 2 + c;
        const float b = be[col];
#pragma unroll
        for (int r = 0; r < 4; ++r) {
            const int row = m0 + ty * 4 + r;
            g_x0[(size_t)row * FEAT + col] = gelu_exact_(acc[r * 2 + c] + b);
        }
    }
}

// =============================================================================
// Gates GEMM + fused LSTM cell.
//   x_t = (t==0 ? x0 : z_{t-1})   <-- autoregressive: sampled z feeds forward
//   gates = x_t @ W_ih^T + h_{t-1} @ W_hh^T + b;  cell update fused in epilogue.
// =============================================================================
template <bool FIRST>
__global__ void __launch_bounds__(256, 2) gates_kernel(
    int t, const float* __restrict__ x,
    const float* __restrict__ W_ih, const float* __restrict__ W_hh,
    const float* __restrict__ b_ih, const float* __restrict__ b_hh)
{
    float*       hout  = (t & 1) ? g_hB : g_hA;
    const float* hprev = (t & 1) ? g_hA : g_hB;

    __shared__ float As[16 * 65];       // [k][row]
    __shared__ float Ws[4 * 16 * 33];   // [gate][k][col]

    const int tid = threadIdx.x;
    const int tx  = tid & 15, ty = tid >> 4;
    const int m0  = blockIdx.x * 64;
    const int n0  = blockIdx.y * 32;

    const int rowl = tid >> 2;
    const int kcl  = (tid & 3) * 4;
    const int q1 = tid,        g1 = q1 >> 7, col1 = (q1 & 127) >> 2, kq1 = (q1 & 3) * 4;
    const int q2 = tid + 256,  g2 = q2 >> 7, col2 = (q2 & 127) >> 2, kq2 = (q2 & 3) * 4;

    const int KT = FIRST ? FEAT : (FEAT + HID);

    float acc[4][8];
#pragma unroll
    for (int g = 0; g < 4; ++g)
#pragma unroll
        for (int i = 0; i < 8; ++i) acc[g][i] = 0.f;

    float4 va, vw1, vw2;
    va  = *reinterpret_cast<const float4*>(&x[(size_t)(m0 + rowl) * FEAT + kcl]);
    vw1 = *reinterpret_cast<const float4*>(&W_ih[(size_t)(g1 * HID + n0 + col1) * FEAT + kq1]);
    vw2 = *reinterpret_cast<const float4*>(&W_ih[(size_t)(g2 * HID + n0 + col2) * FEAT + kq2]);

    for (int kt = 0; kt < KT; kt += 16) {
        As[(kcl + 0) * 65 + rowl] = va.x; As[(kcl + 1) * 65 + rowl] = va.y;
        As[(kcl + 2) * 65 + rowl] = va.z; As[(kcl + 3) * 65 + rowl] = va.w;
        Ws[(g1 * 16 + kq1 + 0) * 33 + col1] = vw1.x;
        Ws[(g1 * 16 + kq1 + 1) * 33 + col1] = vw1.y;
        Ws[(g1 * 16 + kq1 + 2) * 33 + col1] = vw1.z;
        Ws[(g1 * 16 + kq1 + 3) * 33 + col1] = vw1.w;
        Ws[(g2 * 16 + kq2 + 0) * 33 + col2] = vw2.x;
        Ws[(g2 * 16 + kq2 + 1) * 33 + col2] = vw2.y;
        Ws[(g2 * 16 + kq2 + 2) * 33 + col2] = vw2.z;
        Ws[(g2 * 16 + kq2 + 3) * 33 + col2] = vw2.w;
        __syncthreads();

        const int ktn = kt + 16;
        if (ktn < KT) {
            if (ktn < FEAT) {
                va  = *reinterpret_cast<const float4*>(&x[(size_t)(m0 + rowl) * FEAT + ktn + kcl]);
                vw1 = *reinterpret_cast<const float4*>(&W_ih[(size_t)(g1 * HID + n0 + col1) * FEAT + ktn + kq1]);
                vw2 = *reinterpret_cast<const float4*>(&W_ih[(size_t)(g2 * HID + n0 + col2) * FEAT + ktn + kq2]);
            } else {
                const int k0 = ktn - FEAT;
                va  = *reinterpret_cast<const float4*>(&hprev[(size_t)(m0 + rowl) * HID + k0 + kcl]);
                vw1 = *reinterpret_cast<const float4*>(&W_hh[(size_t)(g1 * HID + n0 + col1) * HID + k0 + kq1]);
                vw2 = *reinterpret_cast<const float4*>(&W_hh[(size_t)(g2 * HID + n0 + col2) * HID + k0 + kq2]);
            }
        }

#pragma unroll
        for (int k = 0; k < 16; ++k) {
            const float a0 = As[k * 65 + ty * 4 + 0];
            const float a1 = As[k * 65 + ty * 4 + 1];
            const float a2 = As[k * 65 + ty * 4 + 2];
            const float a3 = As[k * 65 + ty * 4 + 3];
#pragma unroll
            for (int g = 0; g < 4; ++g) {
                const float w0 = Ws[(g * 16 + k) * 33 + tx * 2 + 0];
                const float w1 = Ws[(g * 16 + k) * 33 + tx * 2 + 1];
                acc[g][0] = fmaf(a0, w0, acc[g][0]); acc[g][1] = fmaf(a0, w1, acc[g][1]);
                acc[g][2] = fmaf(a1, w0, acc[g][2]); acc[g][3] = fmaf(a1, w1, acc[g][3]);
                acc[g][4] = fmaf(a2, w0, acc[g][4]); acc[g][5] = fmaf(a2, w1, acc[g][5]);
                acc[g][6] = fmaf(a3, w0, acc[g][6]); acc[g][7] = fmaf(a3, w1, acc[g][7]);
            }
        }
        __syncthreads();
    }

#pragma unroll
    for (int c = 0; c < 2; ++c) {
        const int col = n0 + tx * 2 + c;
        const float bi = b_ih[col]           + b_hh[col];
        const float bf = b_ih[HID + col]     + b_hh[HID + col];
        const float bg = b_ih[2 * HID + col] + b_hh[2 * HID + col];
        const float bo = b_ih[3 * HID + col] + b_hh[3 * HID + col];
#pragma unroll
        for (int r = 0; r < 4; ++r) {
            const int row = m0 + ty * 4 + r;
            const size_t idx = (size_t)row * HID + col;
            const float gi = acc[0][r * 2 + c] + bi;
            const float gf = acc[1][r * 2 + c] + bf;
            const float gg = acc[2][r * 2 + c] + bg;
            const float go = acc[3][r * 2 + c] + bo;
            const float cprev = FIRST ? 0.f : g_c[idx];
            const float cn = sigmoidf_(gf) * cprev + sigmoidf_(gi) * tanhf(gg);
            g_c[idx]  = cn;
            hout[idx] = sigmoidf_(go) * tanhf(cn);
        }
    }
}

// =============================================================================
// Output heads: mu / sigma / z  (z feeds the next step's gates kernel)
// =============================================================================
__global__ void __launch_bounds__(256, 2) out_kernel(
    int t,
    const float* __restrict__ W_mu, const float* __restrict__ W_sp,
    const float* __restrict__ b_mu, const float* __restrict__ b_sp,
    const float* __restrict__ eps,
    float* __restrict__ zs, float* __restrict__ mus, float* __restrict__ sgs)
{
    const float* h = (t & 1) ? g_hB : g_hA;

    __shared__ float As[16 * 65];
    __shared__ float Ws[2 * 16 * 33];

    const int tid = threadIdx.x;
    const int tx  = tid & 15, ty = tid >> 4;
    const int m0  = blockIdx.x * 64;
    const int n0  = blockIdx.y * 32;

    const int rowl = tid >> 2;
    const int kcl  = (tid & 3) * 4;
    const int sw   = tid >> 7;
    const int colw = (tid & 127) >> 2;
    const int kqw  = (tid & 3) * 4;
    const float* Wme = sw ? W_sp : W_mu;

    float acc[2][8];
#pragma unroll
    for (int s = 0; s < 2; ++s)
#pragma unroll
        for (int i = 0; i < 8; ++i) acc[s][i] = 0.f;

    float4 va, vw;
    va = *reinterpret_cast<const float4*>(&h[(size_t)(m0 + rowl) * HID + kcl]);
    vw = *reinterpret_cast<const float4*>(&Wme[(size_t)(n0 + colw) * HID + kqw]);

    for (int k0 = 0; k0 < HID; k0 += 16) {
        As[(kcl + 0) * 65 + rowl] = va.x; As[(kcl + 1) * 65 + rowl] = va.y;
        As[(kcl + 2) * 65 + rowl] = va.z; As[(kcl + 3) * 65 + rowl] = va.w;
        Ws[(sw * 16 + kqw + 0) * 33 + colw] = vw.x;
        Ws[(sw * 16 + kqw + 1) * 33 + colw] = vw.y;
        Ws[(sw * 16 + kqw + 2) * 33 + colw] = vw.z;
        Ws[(sw * 16 + kqw + 3) * 33 + colw] = vw.w;
        __syncthreads();

        const int kn = k0 + 16;
        if (kn < HID) {
            va = *reinterpret_cast<const float4*>(&h[(size_t)(m0 + rowl) * HID + kn + kcl]);
            vw = *reinterpret_cast<const float4*>(&Wme[(size_t)(n0 + colw) * HID + kn + kqw]);
        }

#pragma unroll
        for (int k = 0; k < 16; ++k) {
            const float a0 = As[k * 65 + ty * 4 + 0];
            const float a1 = As[k * 65 + ty * 4 + 1];
            const float a2 = As[k * 65 + ty * 4 + 2];
            const float a3 = As[k * 65 + ty * 4 + 3];
#pragma unroll
            for (int s = 0; s < 2; ++s) {
                const float w0 = Ws[(s * 16 + k) * 33 + tx * 2 + 0];
                const float w1 = Ws[(s * 16 + k) * 33 + tx * 2 + 1];
                acc[s][0] = fmaf(a0, w0, acc[s][0]); acc[s][1] = fmaf(a0, w1, acc[s][1]);
                acc[s][2] = fmaf(a1, w0, acc[s][2]); acc[s][3] = fmaf(a1, w1, acc[s][3]);
                acc[s][4] = fmaf(a2, w0, acc[s][4]); acc[s][5] = fmaf(a2, w1, acc[s][5]);
                acc[s][6] = fmaf(a3, w0, acc[s][6]); acc[s][7] = fmaf(a3, w1, acc[s][7]);
            }
        }
        __syncthreads();
    }

#pragma unroll
    for (int c = 0; c < 2; ++c) {
        const int col = n0 + tx * 2 + c;
        const float bm = b_mu[col];
        const float bs = b_sp[col];
#pragma unroll
        for (int r = 0; r < 4; ++r) {
            const int row = m0 + ty * 4 + r;
            const size_t oidx = (size_t)t * B_SZ * FEAT + (size_t)row * FEAT + col;
            const float mu = acc[0][r * 2 + c] + bm;
            const float sg = softplusf_(acc[1][r * 2 + c] + bs);  // T_TEMP = 1
            zs[oidx]  = mu + sg * eps[oidx];
            mus[oidx] = mu;
            sgs[oidx] = sg;
        }
    }
}

// =============================================================================
// launch
// =============================================================================
extern "C" void kernel_launch(void* const* d_in, const int* in_sizes, int n_in,
                              void* d_out, int out_size)
{
    (void)in_sizes; (void)n_in; (void)out_size;
    const float* S    = (const float*)d_in[0];
    const float* eps  = (const float*)d_in[1];
    // d_in[2] = num_slots (8)
    const float* We   = (const float*)d_in[3];
    const float* be   = (const float*)d_in[4];
    const float* W_ih = (const float*)d_in[5];
    const float* W_hh = (const float*)d_in[6];
    const float* b_ih = (const float*)d_in[7];
    const float* b_hh = (const float*)d_in[8];
    const float* W_mu = (const float*)d_in[9];
    const float* b_mu = (const float*)d_in[10];
    const float* W_sp = (const float*)d_in[11];
    const float* b_sp = (const float*)d_in[12];

    float* out = (float*)d_out;
    const size_t slab = (size_t)NSLOTS * B_SZ * FEAT;
    float* zs  = out;
    float* mus = out + slab;
    float* sgs = out + 2 * slab;

    const dim3 blk(256);
    enc_kernel<<<dim3(B_SZ / 64, FEAT / 32), blk>>>(S, We, be);

    // device-symbol address for g_x0 (host-side &g_x0 is not the device ptr;
    // use cudaGetSymbolAddress once — it's not an allocation)
    static float* x0_ptr = nullptr;
    if (!x0_ptr) cudaGetSymbolAddress((void**)&x0_ptr, g_x0);

    for (int t = 0; t < NSLOTS; ++t) {
        const float* x = (t == 0) ? (const float*)x0_ptr
                                  : zs + (size_t)(t - 1) * B_SZ * FEAT;
        if (t == 0)
            gates_kernel<true><<<dim3(B_SZ / 64, HID / 32), blk>>>(t, x, W_ih, W_hh, b_ih, b_hh);
        else
            gates_kernel<false><<<dim3(B_SZ / 64, HID / 32), blk>>>(t, x, W_ih, W_hh, b_ih, b_hh);

        out_kernel<<<dim3(B_SZ / 64, FEAT / 32), blk>>>(
            t, W_mu, W_sp, b_mu, b_sp, eps, zs, mus, sgs);
    }
}

// round 5
// speedup vs baseline: 2.0117x; 2.0094x over previous
#include <cuda_runtime.h>
#include <cuda_bf16.h>
#include <cstdint>
#include <math.h>

#define B_SZ 16384
#define SCENE 256
#define FEAT 256
#define HID 1024
#define NSLOTS 8
typedef __nv_bfloat16 bf16;

// ---------------- device scratch ---------------------------------------------
__device__ bf16 g_Wg_hi[4096 * 1280];  // [hb16][gate4][hc64][k1280]
__device__ bf16 g_Wg_lo[4096 * 1280];
__device__ bf16 g_Wo_hi[512 * 1024];   // [nb2][mu128|sp128][k1024]
__device__ bf16 g_Wo_lo[512 * 1024];
__device__ bf16 g_x_hi[B_SZ * FEAT];
__device__ bf16 g_x_lo[B_SZ * FEAT];
__device__ bf16 g_hA_hi[B_SZ * HID];
__device__ bf16 g_hA_lo[B_SZ * HID];
__device__ bf16 g_hB_hi[B_SZ * HID];
__device__ bf16 g_hB_lo[B_SZ * HID];
__device__ float g_c[B_SZ * HID];

// ---------------- helpers -----------------------------------------------------
__device__ __forceinline__ uint32_t s2u(const void* p) {
    uint32_t a;
    asm("{.reg .u64 t; cvta.to.shared.u64 t,%1; cvt.u32.u64 %0,t;}" : "=r"(a) : "l"(p));
    return a;
}
#define CP16(dst, src) asm volatile("cp.async.cg.shared.global [%0], [%1], 16;" ::"r"(dst), "l"(src))
#define CPCOMMIT() asm volatile("cp.async.commit_group;" ::: "memory")
#define CPWAIT1() asm volatile("cp.async.wait_group 1;" ::: "memory")

__device__ __forceinline__ void ldsm4(uint32_t* r, uint32_t a) {
    asm volatile("ldmatrix.sync.aligned.m8n8.x4.shared.b16 {%0,%1,%2,%3},[%4];"
                 : "=r"(r[0]), "=r"(r[1]), "=r"(r[2]), "=r"(r[3]) : "r"(a));
}
__device__ __forceinline__ void mma16816(float* c, const uint32_t* a, const uint32_t* b) {
    asm volatile("mma.sync.aligned.m16n8k16.row.col.f32.bf16.bf16.f32 "
                 "{%0,%1,%2,%3},{%4,%5,%6,%7},{%8,%9},{%0,%1,%2,%3};"
                 : "+f"(c[0]), "+f"(c[1]), "+f"(c[2]), "+f"(c[3])
                 : "r"(a[0]), "r"(a[1]), "r"(a[2]), "r"(a[3]), "r"(b[0]), "r"(b[1]));
}

__device__ __forceinline__ float sig_(float x) { return 1.f / (1.f + __expf(-x)); }
__device__ __forceinline__ float tanh_(float x) { return 2.f * sig_(2.f * x) - 1.f; }
__device__ __forceinline__ float sp_(float x) { return fmaxf(x, 0.f) + __logf(1.f + __expf(-fabsf(x))); }
__device__ __forceinline__ void splt(float v, bf16& h, bf16& l) {
    h = __float2bfloat16(v); l = __float2bfloat16(v - __bfloat162float(h));
}

// ---------------- smem layout --------------------------------------------------
// rows padded 64B->80B: conflict-light for ldmatrix (80B = 20 banks)
#define A_STG 10240               // 128 rows * 80B
#define B_STG 20480               // 256 rows * 80B
#define STG   (A_STG + B_STG)     // 30720
#define NSTAGE 3
#define DS_STRIDE 264             // floats
#define OFF_BIAS (128 * DS_STRIDE * 4)   // 135168 (Ds region 0..135168)
#define SMEM_T (OFF_BIAS + 2048)         // 137216

// ---------------- chunk loader -------------------------------------------------
__device__ __forceinline__ void load_chunk(uint32_t stg, const bf16* __restrict__ aP, int aK,
                                           const bf16* __restrict__ bP, int bK, int tid) {
    {   // A: 128 rows x 64B = 512 chunks, 1/thread
        int r = tid >> 2, ch = tid & 3;
        CP16(stg + r * 80 + ch * 16, (const char*)(aP + (size_t)r * aK) + ch * 16);
    }
#pragma unroll
    for (int q = 0; q < 2; ++q) {   // B: 256 rows -> 1024 chunks, 2/thread
        int idx = tid + q * 512;
        int r = idx >> 2, ch = idx & 3;
        CP16(stg + A_STG + r * 80 + ch * 16, (const char*)(bP + (size_t)r * bK) + ch * 16);
    }
}

// ---------------- compute one k32 chunk ----------------------------------------
__device__ __forceinline__ void compute_chunk(uint32_t sa, float acc[2][8][4],
                                              int wm, int wn, int lane) {
    const uint32_t sb = sa + A_STG;
#pragma unroll
    for (int kk = 0; kk < 2; ++kk) {
        uint32_t a[2][4], b[4][4];
#pragma unroll
        for (int i = 0; i < 2; ++i) {
            int row = wm * 32 + i * 16 + (lane & 15);
            ldsm4(a[i], sa + row * 80 + kk * 32 + ((lane >> 4) << 4));
        }
#pragma unroll
        for (int jp = 0; jp < 4; ++jp) {
            int row = wn * 64 + jp * 16 + ((lane & 7) | ((lane >> 4) << 3));
            ldsm4(b[jp], sb + row * 80 + kk * 32 + (((lane >> 3) & 1) << 4));
        }
#pragma unroll
        for (int i = 0; i < 2; ++i)
#pragma unroll
            for (int j = 0; j < 8; ++j)
                mma16816(acc[i][j], a[i], &b[j >> 1][(j & 1) * 2]);
    }
}

__device__ __forceinline__ void store_ds(float* Ds, float acc[2][8][4], int wm, int wn, int lane) {
#pragma unroll
    for (int i = 0; i < 2; ++i)
#pragma unroll
        for (int j = 0; j < 8; ++j) {
            int row = wm * 32 + i * 16 + (lane >> 2);
            int col = wn * 64 + j * 8 + (lane & 3) * 2;
            Ds[row * DS_STRIDE + col]     = acc[i][j][0];
            Ds[row * DS_STRIDE + col + 1] = acc[i][j][1];
            Ds[(row + 8) * DS_STRIDE + col]     = acc[i][j][2];
            Ds[(row + 8) * DS_STRIDE + col + 1] = acc[i][j][3];
        }
}

// ---------------- weight repack -------------------------------------------------
__global__ void conv_weights(const float* __restrict__ Wih, const float* __restrict__ Whh,
                             const float* __restrict__ Wmu, const float* __restrict__ Wsp) {
    int i = blockIdx.x * 256 + threadIdx.x;
    const int NG = 4096 * 1280;
    if (i < NG) {
        int r = i / 1280, k = i - r * 1280;
        int hb = r >> 8, gate = (r >> 6) & 3, hc = r & 63;
        int o = gate * HID + hb * 64 + hc;
        float w = (k < FEAT) ? Wih[(size_t)o * FEAT + k] : Whh[(size_t)o * HID + (k - FEAT)];
        splt(w, g_Wg_hi[i], g_Wg_lo[i]);
    } else {
        int j = i - NG;
        if (j < 512 * 1024) {
            int r = j / 1024, k = j - r * 1024;
            int nb = r >> 8, half = (r >> 7) & 1, hc = r & 127;
            float w = half ? Wsp[(size_t)(nb * 128 + hc) * HID + k]
                           : Wmu[(size_t)(nb * 128 + hc) * HID + k];
            splt(w, g_Wo_hi[j], g_Wo_lo[j]);
        }
    }
}

// ---------------- encoder (SIMT) -------------------------------------------------
__global__ void __launch_bounds__(256, 2) enc_kernel(const float* __restrict__ S,
                                                     const float* __restrict__ We,
                                                     const float* __restrict__ be) {
    __shared__ float As[16 * 65], Ws[16 * 33];
    const int tid = threadIdx.x, tx = tid & 15, ty = tid >> 4;
    const int m0 = blockIdx.x * 64, n0 = blockIdx.y * 32;
    float acc[8];
#pragma unroll
    for (int i = 0; i < 8; ++i) acc[i] = 0.f;
    const int rl = tid >> 2, kl = (tid & 3) * 4;
    for (int k0 = 0; k0 < SCENE; k0 += 16) {
        float4 v = *reinterpret_cast<const float4*>(&S[(size_t)(m0 + rl) * SCENE + k0 + kl]);
        As[(kl + 0) * 65 + rl] = v.x; As[(kl + 1) * 65 + rl] = v.y;
        As[(kl + 2) * 65 + rl] = v.z; As[(kl + 3) * 65 + rl] = v.w;
        if (tid < 128) {
            int c = tid >> 2, kc = (tid & 3) * 4;
            float4 w = *reinterpret_cast<const float4*>(&We[(size_t)(n0 + c) * SCENE + k0 + kc]);
            Ws[(kc + 0) * 33 + c] = w.x; Ws[(kc + 1) * 33 + c] = w.y;
            Ws[(kc + 2) * 33 + c] = w.z; Ws[(kc + 3) * 33 + c] = w.w;
        }
        __syncthreads();
#pragma unroll
        for (int k = 0; k < 16; ++k) {
            float a0 = As[k * 65 + ty * 4], a1 = As[k * 65 + ty * 4 + 1];
            float a2 = As[k * 65 + ty * 4 + 2], a3 = As[k * 65 + ty * 4 + 3];
            float w0 = Ws[k * 33 + tx * 2], w1 = Ws[k * 33 + tx * 2 + 1];
            acc[0] = fmaf(a0, w0, acc[0]); acc[1] = fmaf(a0, w1, acc[1]);
            acc[2] = fmaf(a1, w0, acc[2]); acc[3] = fmaf(a1, w1, acc[3]);
            acc[4] = fmaf(a2, w0, acc[4]); acc[5] = fmaf(a2, w1, acc[5]);
            acc[6] = fmaf(a3, w0, acc[6]); acc[7] = fmaf(a3, w1, acc[7]);
        }
        __syncthreads();
    }
#pragma unroll
    for (int c = 0; c < 2; ++c) {
        const int col = n0 + tx * 2 + c;
        const float b = be[col];
#pragma unroll
        for (int r = 0; r < 4; ++r) {
            const int row = m0 + ty * 4 + r;
            float v = acc[r * 2 + c] + b;
            v = 0.5f * v * (1.f + erff(v * 0.7071067811865476f));
            splt(v, g_x_hi[(size_t)row * FEAT + col], g_x_lo[(size_t)row * FEAT + col]);
        }
    }
}

// ---------------- gates GEMM + fused LSTM cell -----------------------------------
template <bool FIRST>
__global__ void __launch_bounds__(512, 1) gates_mma(int t, const float* __restrict__ bih,
                                                    const float* __restrict__ bhh) {
    extern __shared__ char sm[];
    const uint32_t smu = s2u(sm);
    const int tid = threadIdx.x, lane = tid & 31, wid = tid >> 5;
    const int wm = wid >> 2, wn = wid & 3;
    const int m0 = blockIdx.x * 128, ny = blockIdx.y;

    const bf16* hp_hi = (t & 1) ? g_hA_hi : g_hB_hi;
    const bf16* hp_lo = (t & 1) ? g_hA_lo : g_hB_lo;
    bf16* ho_hi = (t & 1) ? g_hB_hi : g_hA_hi;
    bf16* ho_lo = (t & 1) ? g_hB_lo : g_hA_lo;

    float* bs = reinterpret_cast<float*>(sm + OFF_BIAS);
    if (tid < 256) {
        int gate = tid >> 6, j = ny * 64 + (tid & 63);
        bs[tid] = bih[gate * HID + j] + bhh[gate * HID + j];
    }

    const int NCk = FIRST ? 8 : 40;
    const int NC = 3 * NCk;

    float acc[2][8][4];
#pragma unroll
    for (int i = 0; i < 2; ++i)
#pragma unroll
        for (int j = 0; j < 8; ++j)
#pragma unroll
            for (int e = 0; e < 4; ++e) acc[i][j][e] = 0.f;

    auto resolve_load = [&](int cs, int stage) {
        int term = (cs >= 2 * NCk) ? 2 : ((cs >= NCk) ? 1 : 0);
        int kc = (cs - term * NCk) * 32;
        const bf16* aP; int aK;
        if (FIRST || kc < 256) {
            aP = (term == 1 ? g_x_lo : g_x_hi) + (size_t)m0 * FEAT + kc; aK = FEAT;
        } else {
            aP = (term == 1 ? hp_lo : hp_hi) + (size_t)m0 * HID + (kc - 256); aK = HID;
        }
        const bf16* bP = (term == 2 ? g_Wg_lo : g_Wg_hi) + (size_t)(ny * 256) * 1280 + kc;
        load_chunk(smu + stage * STG, aP, aK, bP, 1280, tid);
    };

    resolve_load(0, 0); CPCOMMIT();
    resolve_load(1, 1); CPCOMMIT();
    for (int cs = 0; cs < NC; ++cs) {
        CPWAIT1();
        __syncthreads();
        compute_chunk(smu + (cs % 3) * STG, acc, wm, wn, lane);
        __syncthreads();
        if (cs + 2 < NC) resolve_load(cs + 2, (cs + 2) % 3);
        CPCOMMIT();
    }

    // epilogue: D -> smem -> fused LSTM cell
    float* Ds = reinterpret_cast<float*>(sm);
    store_ds(Ds, acc, wm, wn, lane);
    __syncthreads();

    const int row = tid >> 2;
    const int hc0 = (tid & 3) * 16;
    const int gr = m0 + row;
    const size_t base = (size_t)gr * HID + ny * 64 + hc0;
#pragma unroll
    for (int q = 0; q < 4; ++q) {
        const int hc = hc0 + q * 4;
        float4 cold;
        if (!FIRST) cold = *reinterpret_cast<const float4*>(&g_c[base + q * 4]);
        float cn[4];
        union { bf16 b[4]; uint2 u; } Hh, Hl;
#pragma unroll
        for (int e = 0; e < 4; ++e) {
            const float gi = Ds[row * DS_STRIDE + 0 * 64 + hc + e] + bs[0 * 64 + hc + e];
            const float gf = Ds[row * DS_STRIDE + 1 * 64 + hc + e] + bs[1 * 64 + hc + e];
            const float gg = Ds[row * DS_STRIDE + 2 * 64 + hc + e] + bs[2 * 64 + hc + e];
            const float go = Ds[row * DS_STRIDE + 3 * 64 + hc + e] + bs[3 * 64 + hc + e];
            const float cp = FIRST ? 0.f : ((const float*)&cold)[e];
            const float c2 = sig_(gf) * cp + sig_(gi) * tanh_(gg);
            cn[e] = c2;
            splt(sig_(go) * tanh_(c2), Hh.b[e], Hl.b[e]);
        }
        *reinterpret_cast<float4*>(&g_c[base + q * 4]) = *reinterpret_cast<float4*>(cn);
        *reinterpret_cast<uint2*>(&ho_hi[base + q * 4]) = Hh.u;
        *reinterpret_cast<uint2*>(&ho_lo[base + q * 4]) = Hl.u;
    }
}

// ---------------- heads GEMM: mu | softplus sigma | z ------------------------------
__global__ void __launch_bounds__(512, 1) heads_mma(int t, const float* __restrict__ bmu,
                                                    const float* __restrict__ bsp,
                                                    const float* __restrict__ eps,
                                                    float* __restrict__ zs,
                                                    float* __restrict__ mus,
                                                    float* __restrict__ sgs) {
    extern __shared__ char sm[];
    const uint32_t smu = s2u(sm);
    const int tid = threadIdx.x, lane = tid & 31, wid = tid >> 5;
    const int wm = wid >> 2, wn = wid & 3;
    const int m0 = blockIdx.x * 128, nb = blockIdx.y;

    const bf16* hc_hi = (t & 1) ? g_hB_hi : g_hA_hi;
    const bf16* hc_lo = (t & 1) ? g_hB_lo : g_hA_lo;

    float* bs = reinterpret_cast<float*>(sm + OFF_BIAS);
    if (tid < 256) {
        int half = tid >> 7, c = tid & 127;
        bs[tid] = half ? bsp[nb * 128 + c] : bmu[nb * 128 + c];
    }

    const int NCk = 32, NC = 96;
    float acc[2][8][4];
#pragma unroll
    for (int i = 0; i < 2; ++i)
#pragma unroll
        for (int j = 0; j < 8; ++j)
#pragma unroll
            for (int e = 0; e < 4; ++e) acc[i][j][e] = 0.f;

    auto resolve_load = [&](int cs, int stage) {
        int term = (cs >= 2 * NCk) ? 2 : ((cs >= NCk) ? 1 : 0);
        int kc = (cs - term * NCk) * 32;
        const bf16* aP = (term == 1 ? hc_lo : hc_hi) + (size_t)m0 * HID + kc;
        const bf16* bP = (term == 2 ? g_Wo_lo : g_Wo_hi) + (size_t)(nb * 256) * 1024 + kc;
        load_chunk(smu + stage * STG, aP, HID, bP, 1024, tid);
    };

    resolve_load(0, 0); CPCOMMIT();
    resolve_load(1, 1); CPCOMMIT();
    for (int cs = 0; cs < NC; ++cs) {
        CPWAIT1();
        __syncthreads();
        compute_chunk(smu + (cs % 3) * STG, acc, wm, wn, lane);
        __syncthreads();
        if (cs + 2 < NC) resolve_load(cs + 2, (cs + 2) % 3);
        CPCOMMIT();
    }

    float* Ds = reinterpret_cast<float*>(sm);
    store_ds(Ds, acc, wm, wn, lane);
    __syncthreads();

    const int row = tid >> 2;
    const int hc0 = (tid & 3) * 32;
    const int gr = m0 + row;
#pragma unroll
    for (int q = 0; q < 8; ++q) {
        const int hc = hc0 + q * 4;
        const size_t o = (size_t)t * B_SZ * FEAT + (size_t)gr * FEAT + nb * 128 + hc;
        const size_t xb = (size_t)gr * FEAT + nb * 128 + hc;
        float4 ev = *reinterpret_cast<const float4*>(&eps[o]);
        float zv[4], mv[4], sv[4];
        union { bf16 b[4]; uint2 u; } Zh, Zl;
#pragma unroll
        for (int e = 0; e < 4; ++e) {
            const float mu = Ds[row * DS_STRIDE + hc + e] + bs[hc + e];
            const float sg = sp_(Ds[row * DS_STRIDE + 128 + hc + e] + bs[128 + hc + e]);
            const float z = mu + sg * ((const float*)&ev)[e];
            mv[e] = mu; sv[e] = sg; zv[e] = z;
            splt(z, Zh.b[e], Zl.b[e]);
        }
        *reinterpret_cast<float4*>(&zs[o])  = *reinterpret_cast<float4*>(zv);
        *reinterpret_cast<float4*>(&mus[o]) = *reinterpret_cast<float4*>(mv);
        *reinterpret_cast<float4*>(&sgs[o]) = *reinterpret_cast<float4*>(sv);
        *reinterpret_cast<uint2*>(&g_x_hi[xb]) = Zh.u;
        *reinterpret_cast<uint2*>(&g_x_lo[xb]) = Zl.u;
    }
}

// ---------------- launch ------------------------------------------------------------
extern "C" void kernel_launch(void* const* d_in, const int* in_sizes, int n_in,
                              void* d_out, int out_size) {
    (void)in_sizes; (void)n_in; (void)out_size;
    const float* S   = (const float*)d_in[0];
    const float* eps = (const float*)d_in[1];
    const float* We  = (const float*)d_in[3];
    const float* be  = (const float*)d_in[4];
    const float* Wih = (const float*)d_in[5];
    const float* Whh = (const float*)d_in[6];
    const float* bih = (const float*)d_in[7];
    const float* bhh = (const float*)d_in[8];
    const float* Wmu = (const float*)d_in[9];
    const float* bmu = (const float*)d_in[10];
    const float* Wsp = (const float*)d_in[11];
    const float* bsp = (const float*)d_in[12];

    float* out = (float*)d_out;
    const size_t slab = (size_t)NSLOTS * B_SZ * FEAT;
    float *zs = out, *mus = out + slab, *sgs = out + 2 * slab;

    static bool attr_done = false;
    if (!attr_done) {
        cudaFuncSetAttribute(gates_mma<true>,  cudaFuncAttributeMaxDynamicSharedMemorySize, SMEM_T);
        cudaFuncSetAttribute(gates_mma<false>, cudaFuncAttributeMaxDynamicSharedMemorySize, SMEM_T);
        cudaFuncSetAttribute(heads_mma,        cudaFuncAttributeMaxDynamicSharedMemorySize, SMEM_T);
        attr_done = true;
    }

    conv_weights<<<22528, 256>>>(Wih, Whh, Wmu, Wsp);
    enc_kernel<<<dim3(B_SZ / 64, FEAT / 32), 256>>>(S, We, be);

    for (int t = 0; t < NSLOTS; ++t) {
        if (t == 0)
            gates_mma<true><<<dim3(B_SZ / 128, 16), 512, SMEM_T>>>(t, bih, bhh);
        else
            gates_mma<false><<<dim3(B_SZ / 128, 16), 512, SMEM_T>>>(t, bih, bhh);
        heads_mma<<<dim3(B_SZ / 128, 2), 512, SMEM_T>>>(t, bmu, bsp, eps, zs, mus, sgs);
    }
}

// round 6
// speedup vs baseline: 2.7512x; 1.3676x over previous
#include <cuda_runtime.h>
#include <cuda_bf16.h>
#include <cstdint>
#include <math.h>

#define B_SZ 16384
#define SCENE 256
#define FEAT 256
#define HID 1024
#define NSLOTS 8
typedef __nv_bfloat16 bf16;

// ---------------- device scratch ---------------------------------------------
// gates weights packed: row = ny*256 + wn*64 + hcg*32 + gate*8 + h8 ; K = 1280
__device__ bf16 g_Wg_hi[4096 * 1280];
__device__ bf16 g_Wg_lo[4096 * 1280];
// heads weights packed: row = nb*256 + wn*64 + hcg*16 + head*8 + h8 ; K = 1024
__device__ bf16 g_Wo_hi[512 * 1024];
__device__ bf16 g_Wo_lo[512 * 1024];
__device__ bf16 g_x_hi[B_SZ * FEAT];
__device__ bf16 g_x_lo[B_SZ * FEAT];
__device__ bf16 g_hA_hi[B_SZ * HID];
__device__ bf16 g_hA_lo[B_SZ * HID];
__device__ bf16 g_hB_hi[B_SZ * HID];
__device__ bf16 g_hB_lo[B_SZ * HID];
__device__ float g_c[B_SZ * HID];

// ---------------- helpers -----------------------------------------------------
__device__ __forceinline__ uint32_t s2u(const void* p) {
    uint32_t a;
    asm("{.reg .u64 t; cvta.to.shared.u64 t,%1; cvt.u32.u64 %0,t;}" : "=r"(a) : "l"(p));
    return a;
}
#define CP16(dst, src) asm volatile("cp.async.cg.shared.global [%0], [%1], 16;" ::"r"(dst), "l"(src))
#define CPCOMMIT() asm volatile("cp.async.commit_group;" ::: "memory")
#define CPWAIT2() asm volatile("cp.async.wait_group 2;" ::: "memory")

__device__ __forceinline__ void ldsm4(uint32_t* r, uint32_t a) {
    asm volatile("ldmatrix.sync.aligned.m8n8.x4.shared.b16 {%0,%1,%2,%3},[%4];"
                 : "=r"(r[0]), "=r"(r[1]), "=r"(r[2]), "=r"(r[3]) : "r"(a));
}
__device__ __forceinline__ void mma16816(float* c, const uint32_t* a, const uint32_t* b) {
    asm volatile("mma.sync.aligned.m16n8k16.row.col.f32.bf16.bf16.f32 "
                 "{%0,%1,%2,%3},{%4,%5,%6,%7},{%8,%9},{%0,%1,%2,%3};"
                 : "+f"(c[0]), "+f"(c[1]), "+f"(c[2]), "+f"(c[3])
                 : "r"(a[0]), "r"(a[1]), "r"(a[2]), "r"(a[3]), "r"(b[0]), "r"(b[1]));
}

__device__ __forceinline__ float sig_(float x) { return 1.f / (1.f + __expf(-x)); }
__device__ __forceinline__ float tanh_(float x) { return 2.f * sig_(2.f * x) - 1.f; }
__device__ __forceinline__ float sp_(float x) { return fmaxf(x, 0.f) + __logf(1.f + __expf(-fabsf(x))); }
__device__ __forceinline__ void splt(float v, bf16& h, bf16& l) {
    h = __float2bfloat16(v); l = __float2bfloat16(v - __bfloat162float(h));
}

// ---------------- smem layout ---------------------------------------------------
// per stage (k32 chunk): A_hi | A_lo (128 rows x 80B each) , B_hi | B_lo (256 x 80B)
#define A_SUB 10240
#define B_SUB 20480
#define OFF_BHI (2 * A_SUB)             // 20480
#define OFF_BLO (2 * A_SUB + B_SUB)     // 40960
#define STG 61440
#define OFF_BIAS (3 * STG)              // 184320
#define SMEM_T (OFF_BIAS + 1024)        // 185344

// ---------------- fused chunk loader (hi+lo, A+B) --------------------------------
__device__ __forceinline__ void load_chunk(uint32_t stg,
                                           const bf16* __restrict__ aHi, const bf16* __restrict__ aLo, int aK,
                                           const bf16* __restrict__ bHi, const bf16* __restrict__ bLo, int bK,
                                           int tid) {
    const int r = tid >> 2, ch = tid & 3;       // A: 128 rows x 4 chunks
    CP16(stg + r * 80 + ch * 16, (const char*)(aHi + (size_t)r * aK) + ch * 16);
    CP16(stg + A_SUB + r * 80 + ch * 16, (const char*)(aLo + (size_t)r * aK) + ch * 16);
#pragma unroll
    for (int q = 0; q < 2; ++q) {               // B: 256 rows x 4 chunks = 1024 lines
        const int idx = tid + q * 512;
        const int br = idx >> 2, bch = idx & 3;
        CP16(stg + OFF_BHI + br * 80 + bch * 16, (const char*)(bHi + (size_t)br * bK) + bch * 16);
        CP16(stg + OFF_BLO + br * 80 + bch * 16, (const char*)(bLo + (size_t)br * bK) + bch * 16);
    }
}

// ---------------- compute one fused k32 chunk (3 split terms) --------------------
__device__ __forceinline__ void compute_chunk(uint32_t sa, float acc[2][8][4],
                                              int wm, int wn, int lane) {
#pragma unroll
    for (int kk = 0; kk < 2; ++kk) {
        uint32_t ahi[2][4], alo[2][4];
#pragma unroll
        for (int i = 0; i < 2; ++i) {
            const int row = wm * 32 + i * 16 + (lane & 15);
            const uint32_t off = row * 80 + kk * 32 + ((lane >> 4) << 4);
            ldsm4(ahi[i], sa + off);
            ldsm4(alo[i], sa + A_SUB + off);
        }
#pragma unroll
        for (int jp = 0; jp < 4; ++jp) {
            const int brow = wn * 64 + jp * 16 + ((lane & 7) | ((lane >> 4) << 3));
            const uint32_t boff = brow * 80 + kk * 32 + (((lane >> 3) & 1) << 4);
            uint32_t bh[4], bl[4];
            ldsm4(bh, sa + OFF_BHI + boff);
#pragma unroll
            for (int i = 0; i < 2; ++i) {
                mma16816(acc[i][jp * 2 + 0], ahi[i], &bh[0]);
                mma16816(acc[i][jp * 2 + 1], ahi[i], &bh[2]);
                mma16816(acc[i][jp * 2 + 0], alo[i], &bh[0]);
                mma16816(acc[i][jp * 2 + 1], alo[i], &bh[2]);
            }
            ldsm4(bl, sa + OFF_BLO + boff);
#pragma unroll
            for (int i = 0; i < 2; ++i) {
                mma16816(acc[i][jp * 2 + 0], ahi[i], &bl[0]);
                mma16816(acc[i][jp * 2 + 1], ahi[i], &bl[2]);
            }
        }
    }
}

// ---------------- weight repack ---------------------------------------------------
__global__ void conv_weights(const float* __restrict__ Wih, const float* __restrict__ Whh,
                             const float* __restrict__ Wmu, const float* __restrict__ Wsp) {
    int i = blockIdx.x * 256 + threadIdx.x;
    const int NG = 4096 * 1280;
    if (i < NG) {
        int r = i / 1280, k = i - r * 1280;
        int ny = r >> 8, w = r & 255;
        int wn = w >> 6, hcg = (w >> 5) & 1, gate = (w >> 3) & 3, h8 = w & 7;
        int hidden = ny * 64 + wn * 16 + hcg * 8 + h8;
        int o = gate * HID + hidden;
        float v = (k < FEAT) ? Wih[(size_t)o * FEAT + k] : Whh[(size_t)o * HID + (k - FEAT)];
        splt(v, g_Wg_hi[i], g_Wg_lo[i]);
    } else {
        int j = i - NG;
        if (j < 512 * 1024) {
            int r = j / 1024, k = j - r * 1024;
            int nb = r >> 8, w = r & 255;
            int wn = w >> 6, hcg = (w >> 4) & 3, head = (w >> 3) & 1, h8 = w & 7;
            int f = nb * 128 + wn * 32 + hcg * 8 + h8;
            float v = head ? Wsp[(size_t)f * HID + k] : Wmu[(size_t)f * HID + k];
            splt(v, g_Wo_hi[j], g_Wo_lo[j]);
        }
    }
}

// ---------------- encoder (SIMT fp32) ----------------------------------------------
__global__ void __launch_bounds__(256, 2) enc_kernel(const float* __restrict__ S,
                                                     const float* __restrict__ We,
                                                     const float* __restrict__ be) {
    __shared__ float As[16 * 65], Ws[16 * 33];
    const int tid = threadIdx.x, tx = tid & 15, ty = tid >> 4;
    const int m0 = blockIdx.x * 64, n0 = blockIdx.y * 32;
    float acc[8];
#pragma unroll
    for (int i = 0; i < 8; ++i) acc[i] = 0.f;
    const int rl = tid >> 2, kl = (tid & 3) * 4;
    for (int k0 = 0; k0 < SCENE; k0 += 16) {
        float4 v = *reinterpret_cast<const float4*>(&S[(size_t)(m0 + rl) * SCENE + k0 + kl]);
        As[(kl + 0) * 65 + rl] = v.x; As[(kl + 1) * 65 + rl] = v.y;
        As[(kl + 2) * 65 + rl] = v.z; As[(kl + 3) * 65 + rl] = v.w;
        if (tid < 128) {
            int c = tid >> 2, kc = (tid & 3) * 4;
            float4 w = *reinterpret_cast<const float4*>(&We[(size_t)(n0 + c) * SCENE + k0 + kc]);
            Ws[(kc + 0) * 33 + c] = w.x; Ws[(kc + 1) * 33 + c] = w.y;
            Ws[(kc + 2) * 33 + c] = w.z; Ws[(kc + 3) * 33 + c] = w.w;
        }
        __syncthreads();
#pragma unroll
        for (int k = 0; k < 16; ++k) {
            float a0 = As[k * 65 + ty * 4], a1 = As[k * 65 + ty * 4 + 1];
            float a2 = As[k * 65 + ty * 4 + 2], a3 = As[k * 65 + ty * 4 + 3];
            float w0 = Ws[k * 33 + tx * 2], w1 = Ws[k * 33 + tx * 2 + 1];
            acc[0] = fmaf(a0, w0, acc[0]); acc[1] = fmaf(a0, w1, acc[1]);
            acc[2] = fmaf(a1, w0, acc[2]); acc[3] = fmaf(a1, w1, acc[3]);
            acc[4] = fmaf(a2, w0, acc[4]); acc[5] = fmaf(a2, w1, acc[5]);
            acc[6] = fmaf(a3, w0, acc[6]); acc[7] = fmaf(a3, w1, acc[7]);
        }
        __syncthreads();
    }
#pragma unroll
    for (int c = 0; c < 2; ++c) {
        const int col = n0 + tx * 2 + c;
        const float b = be[col];
#pragma unroll
        for (int r = 0; r < 4; ++r) {
            const int row = m0 + ty * 4 + r;
            float v = acc[r * 2 + c] + b;
            v = 0.5f * v * (1.f + erff(v * 0.7071067811865476f));
            splt(v, g_x_hi[(size_t)row * FEAT + col], g_x_lo[(size_t)row * FEAT + col]);
        }
    }
}

// ---------------- gates GEMM + in-register LSTM cell --------------------------------
template <bool FIRST>
__global__ void __launch_bounds__(512, 1) gates_mma(int t, const float* __restrict__ bih,
                                                    const float* __restrict__ bhh) {
    extern __shared__ char sm[];
    const uint32_t smu = s2u(sm);
    const int tid = threadIdx.x, lane = tid & 31, wid = tid >> 5;
    const int wm = wid >> 2, wn = wid & 3;
    const int m0 = blockIdx.x * 128, ny = blockIdx.y;

    const bf16* hp_hi = (t & 1) ? g_hA_hi : g_hB_hi;
    const bf16* hp_lo = (t & 1) ? g_hA_lo : g_hB_lo;
    bf16* ho_hi = (t & 1) ? g_hB_hi : g_hA_hi;
    bf16* ho_lo = (t & 1) ? g_hB_lo : g_hA_lo;

    float* bs = reinterpret_cast<float*>(sm + OFF_BIAS);
    if (tid < 256) {
        int wn2 = tid >> 6, hcg = (tid >> 5) & 1, gate = (tid >> 3) & 3, h8 = tid & 7;
        int hidden = ny * 64 + wn2 * 16 + hcg * 8 + h8;
        bs[tid] = bih[gate * HID + hidden] + bhh[gate * HID + hidden];
    }

    const int NC = FIRST ? 8 : 40;
    float acc[2][8][4];
#pragma unroll
    for (int i = 0; i < 2; ++i)
#pragma unroll
        for (int j = 0; j < 8; ++j)
#pragma unroll
            for (int e = 0; e < 4; ++e) acc[i][j][e] = 0.f;

    auto issue_load = [&](int cs) {
        const int kc = cs * 32;
        const bf16 *aH, *aL; int aK;
        if (FIRST || kc < 256) {
            aH = g_x_hi + (size_t)m0 * FEAT + kc;
            aL = g_x_lo + (size_t)m0 * FEAT + kc; aK = FEAT;
        } else {
            aH = hp_hi + (size_t)m0 * HID + (kc - 256);
            aL = hp_lo + (size_t)m0 * HID + (kc - 256); aK = HID;
        }
        const size_t bo = (size_t)(ny * 256) * 1280 + kc;
        load_chunk(smu + (cs % 3) * STG, aH, aL, aK, g_Wg_hi + bo, g_Wg_lo + bo, 1280, tid);
        CPCOMMIT();
    };

    issue_load(0); issue_load(1);
    if (NC > 2) issue_load(2); else CPCOMMIT();
    for (int cs = 0; cs < NC; ++cs) {
        CPWAIT2();
        __syncthreads();
        compute_chunk(smu + (cs % 3) * STG, acc, wm, wn, lane);
        __syncthreads();
        if (cs + 3 < NC) issue_load(cs + 3); else CPCOMMIT();
    }

    // in-register LSTM cell epilogue: j = hcg*4 + gate
    const int lane4 = lane >> 2, lq = lane & 3;
#pragma unroll
    for (int i = 0; i < 2; ++i)
#pragma unroll
        for (int rp = 0; rp < 2; ++rp) {
            const int row = m0 + wm * 32 + i * 16 + lane4 + rp * 8;
#pragma unroll
            for (int hcg = 0; hcg < 2; ++hcg) {
                const int h8b = lq * 2;
                const int hidden = ny * 64 + wn * 16 + hcg * 8 + h8b;
                const size_t base = (size_t)row * HID + hidden;
                const int bb = wn * 64 + hcg * 32 + h8b;
                float2 cold = make_float2(0.f, 0.f);
                if (!FIRST) cold = *reinterpret_cast<const float2*>(&g_c[base]);
                float cn[2];
                union { bf16 b[2]; uint32_t u; } Hh, Hl;
#pragma unroll
                for (int eb = 0; eb < 2; ++eb) {
                    const int e = rp * 2 + eb;
                    const float gi = acc[i][hcg * 4 + 0][e] + bs[bb + 0 + eb];
                    const float gf = acc[i][hcg * 4 + 1][e] + bs[bb + 8 + eb];
                    const float gg = acc[i][hcg * 4 + 2][e] + bs[bb + 16 + eb];
                    const float go = acc[i][hcg * 4 + 3][e] + bs[bb + 24 + eb];
                    const float cp = FIRST ? 0.f : (eb ? cold.y : cold.x);
                    const float c2 = sig_(gf) * cp + sig_(gi) * tanh_(gg);
                    cn[eb] = c2;
                    splt(sig_(go) * tanh_(c2), Hh.b[eb], Hl.b[eb]);
                }
                *reinterpret_cast<float2*>(&g_c[base]) = make_float2(cn[0], cn[1]);
                *reinterpret_cast<uint32_t*>(&ho_hi[base]) = Hh.u;
                *reinterpret_cast<uint32_t*>(&ho_lo[base]) = Hl.u;
            }
        }
}

// ---------------- heads GEMM: mu | softplus sigma | z --------------------------------
__global__ void __launch_bounds__(512, 1) heads_mma(int t, const float* __restrict__ bmu,
                                                    const float* __restrict__ bsp,
                                                    const float* __restrict__ eps,
                                                    float* __restrict__ zs,
                                                    float* __restrict__ mus,
                                                    float* __restrict__ sgs) {
    extern __shared__ char sm[];
    const uint32_t smu = s2u(sm);
    const int tid = threadIdx.x, lane = tid & 31, wid = tid >> 5;
    const int wm = wid >> 2, wn = wid & 3;
    const int m0 = blockIdx.x * 128, nb = blockIdx.y;

    const bf16* hc_hi = (t & 1) ? g_hB_hi : g_hA_hi;
    const bf16* hc_lo = (t & 1) ? g_hB_lo : g_hA_lo;

    float* bs = reinterpret_cast<float*>(sm + OFF_BIAS);
    if (tid < 256) {
        int wn2 = tid >> 6, hcg = (tid >> 4) & 3, head = (tid >> 3) & 1, h8 = tid & 7;
        int f = nb * 128 + wn2 * 32 + hcg * 8 + h8;
        bs[tid] = head ? bsp[f] : bmu[f];
    }

    const int NC = 32;
    float acc[2][8][4];
#pragma unroll
    for (int i = 0; i < 2; ++i)
#pragma unroll
        for (int j = 0; j < 8; ++j)
#pragma unroll
            for (int e = 0; e < 4; ++e) acc[i][j][e] = 0.f;

    auto issue_load = [&](int cs) {
        const int kc = cs * 32;
        const bf16* aH = hc_hi + (size_t)m0 * HID + kc;
        const bf16* aL = hc_lo + (size_t)m0 * HID + kc;
        const size_t bo = (size_t)(nb * 256) * 1024 + kc;
        load_chunk(smu + (cs % 3) * STG, aH, aL, HID, g_Wo_hi + bo, g_Wo_lo + bo, 1024, tid);
        CPCOMMIT();
    };

    issue_load(0); issue_load(1); issue_load(2);
    for (int cs = 0; cs < NC; ++cs) {
        CPWAIT2();
        __syncthreads();
        compute_chunk(smu + (cs % 3) * STG, acc, wm, wn, lane);
        __syncthreads();
        if (cs + 3 < NC) issue_load(cs + 3); else CPCOMMIT();
    }

    // in-register heads epilogue: j = hcg*2 + head
    const int lane4 = lane >> 2, lq = lane & 3;
#pragma unroll
    for (int i = 0; i < 2; ++i)
#pragma unroll
        for (int rp = 0; rp < 2; ++rp) {
            const int row = m0 + wm * 32 + i * 16 + lane4 + rp * 8;
#pragma unroll
            for (int hcg = 0; hcg < 4; ++hcg) {
                const int h8b = lq * 2;
                const int f = nb * 128 + wn * 32 + hcg * 8 + h8b;
                const size_t o = (size_t)t * B_SZ * FEAT + (size_t)row * FEAT + f;
                const size_t xb = (size_t)row * FEAT + f;
                const int bb = wn * 64 + hcg * 16 + h8b;
                const float2 ev = *reinterpret_cast<const float2*>(&eps[o]);
                float zv[2], mv[2], sv[2];
                union { bf16 b[2]; uint32_t u; } Zh, Zl;
#pragma unroll
                for (int eb = 0; eb < 2; ++eb) {
                    const int e = rp * 2 + eb;
                    const float mu = acc[i][hcg * 2 + 0][e] + bs[bb + 0 + eb];
                    const float sg = sp_(acc[i][hcg * 2 + 1][e] + bs[bb + 8 + eb]);
                    const float z = mu + sg * (eb ? ev.y : ev.x);
                    mv[eb] = mu; sv[eb] = sg; zv[eb] = z;
                    splt(z, Zh.b[eb], Zl.b[eb]);
                }
                *reinterpret_cast<float2*>(&zs[o])  = make_float2(zv[0], zv[1]);
                *reinterpret_cast<float2*>(&mus[o]) = make_float2(mv[0], mv[1]);
                *reinterpret_cast<float2*>(&sgs[o]) = make_float2(sv[0], sv[1]);
                *reinterpret_cast<uint32_t*>(&g_x_hi[xb]) = Zh.u;
                *reinterpret_cast<uint32_t*>(&g_x_lo[xb]) = Zl.u;
            }
        }
}

// ---------------- launch --------------------------------------------------------------
extern "C" void kernel_launch(void* const* d_in, const int* in_sizes, int n_in,
                              void* d_out, int out_size) {
    (void)in_sizes; (void)n_in; (void)out_size;
    const float* S   = (const float*)d_in[0];
    const float* eps = (const float*)d_in[1];
    const float* We  = (const float*)d_in[3];
    const float* be  = (const float*)d_in[4];
    const float* Wih = (const float*)d_in[5];
    const float* Whh = (const float*)d_in[6];
    const float* bih = (const float*)d_in[7];
    const float* bhh = (const float*)d_in[8];
    const float* Wmu = (const float*)d_in[9];
    const float* bmu = (const float*)d_in[10];
    const float* Wsp = (const float*)d_in[11];
    const float* bsp = (const float*)d_in[12];

    float* out = (float*)d_out;
    const size_t slab = (size_t)NSLOTS * B_SZ * FEAT;
    float *zs = out, *mus = out + slab, *sgs = out + 2 * slab;

    static bool attr_done = false;
    if (!attr_done) {
        cudaFuncSetAttribute(gates_mma<true>,  cudaFuncAttributeMaxDynamicSharedMemorySize, SMEM_T);
        cudaFuncSetAttribute(gates_mma<false>, cudaFuncAttributeMaxDynamicSharedMemorySize, SMEM_T);
        cudaFuncSetAttribute(heads_mma,        cudaFuncAttributeMaxDynamicSharedMemorySize, SMEM_T);
        attr_done = true;
    }

    conv_weights<<<22528, 256>>>(Wih, Whh, Wmu, Wsp);
    enc_kernel<<<dim3(B_SZ / 64, FEAT / 32), 256>>>(S, We, be);

    for (int t = 0; t < NSLOTS; ++t) {
        if (t == 0)
            gates_mma<true><<<dim3(B_SZ / 128, 16), 512, SMEM_T>>>(t, bih, bhh);
        else
            gates_mma<false><<<dim3(B_SZ / 128, 16), 512, SMEM_T>>>(t, bih, bhh);
        heads_mma<<<dim3(B_SZ / 128, 2), 512, SMEM_T>>>(t, bmu, bsp, eps, zs, mus, sgs);
    }
}

// round 7
// speedup vs baseline: 3.0659x; 1.1144x over previous
#include <cuda_runtime.h>
#include <cuda_bf16.h>
#include <cstdint>
#include <math.h>

#define B_SZ 16384
#define SCENE 256
#define FEAT 256
#define HID 1024
#define NSLOTS 8
typedef __nv_bfloat16 bf16;

// ---------------- device scratch ---------------------------------------------
// gates weights packed: row = ny*128 + wn*64 + hcg*32 + gate*8 + h8 ; K = 1280
// (hidden unit = ny*32 + wn*16 + hcg*8 + h8)
__device__ bf16 g_Wg_hi[4096 * 1280];
__device__ bf16 g_Wg_lo[4096 * 1280];
// heads weights packed: row = nb*128 + wn*64 + hcg*16 + head*8 + h8 ; K = 1024
// (feature = nb*64 + wn*32 + hcg*8 + h8)
__device__ bf16 g_Wo_hi[512 * 1024];
__device__ bf16 g_Wo_lo[512 * 1024];
__device__ bf16 g_x_hi[B_SZ * FEAT];
__device__ bf16 g_x_lo[B_SZ * FEAT];
__device__ bf16 g_hA_hi[B_SZ * HID];
__device__ bf16 g_hA_lo[B_SZ * HID];
__device__ bf16 g_hB_hi[B_SZ * HID];
__device__ bf16 g_hB_lo[B_SZ * HID];
__device__ float g_c[B_SZ * HID];

// ---------------- helpers -----------------------------------------------------
__device__ __forceinline__ uint32_t s2u(const void* p) {
    uint32_t a;
    asm("{.reg .u64 t; cvta.to.shared.u64 t,%1; cvt.u32.u64 %0,t;}" : "=r"(a) : "l"(p));
    return a;
}
#define CP16(dst, src) asm volatile("cp.async.cg.shared.global [%0], [%1], 16;" ::"r"(dst), "l"(src))
#define CPCOMMIT() asm volatile("cp.async.commit_group;" ::: "memory")
#define CPWAIT1() asm volatile("cp.async.wait_group 1;" ::: "memory")

__device__ __forceinline__ void ldsm4(uint32_t* r, uint32_t a) {
    asm volatile("ldmatrix.sync.aligned.m8n8.x4.shared.b16 {%0,%1,%2,%3},[%4];"
                 : "=r"(r[0]), "=r"(r[1]), "=r"(r[2]), "=r"(r[3]) : "r"(a));
}
__device__ __forceinline__ void mma16816(float* c, const uint32_t* a, const uint32_t* b) {
    asm volatile("mma.sync.aligned.m16n8k16.row.col.f32.bf16.bf16.f32 "
                 "{%0,%1,%2,%3},{%4,%5,%6,%7},{%8,%9},{%0,%1,%2,%3};"
                 : "+f"(c[0]), "+f"(c[1]), "+f"(c[2]), "+f"(c[3])
                 : "r"(a[0]), "r"(a[1]), "r"(a[2]), "r"(a[3]), "r"(b[0]), "r"(b[1]));
}

__device__ __forceinline__ float sig_(float x) { return 1.f / (1.f + __expf(-x)); }
__device__ __forceinline__ float tanh_(float x) { return 2.f * sig_(2.f * x) - 1.f; }
__device__ __forceinline__ float sp_(float x) { return fmaxf(x, 0.f) + __logf(1.f + __expf(-fabsf(x))); }
__device__ __forceinline__ void splt(float v, bf16& h, bf16& l) {
    h = __float2bfloat16(v); l = __float2bfloat16(v - __bfloat162float(h));
}

// ---------------- smem layout ---------------------------------------------------
// per stage (k32 chunk, 128x128 tile): A_hi | A_lo | B_hi | B_lo, each 128 rows x 80B
#define SUB 10240
#define OFF_ALO SUB
#define OFF_BHI (2 * SUB)
#define OFF_BLO (3 * SUB)
#define STG (4 * SUB)               // 40960
#define OFF_BIAS (2 * STG)          // 81920
#define SMEM_T (OFF_BIAS + 512)     // 82432  -> 2 CTAs/SM

// ---------------- fused chunk loader (hi+lo, A+B), 256 threads -------------------
__device__ __forceinline__ void load_chunk(uint32_t stg,
                                           const bf16* __restrict__ aHi, const bf16* __restrict__ aLo, int aK,
                                           const bf16* __restrict__ bHi, const bf16* __restrict__ bLo, int bK,
                                           int tid) {
#pragma unroll
    for (int q = 0; q < 2; ++q) {
        const int idx = tid + q * 256;      // 512 lines: 128 rows x 4 chunks
        const int r = idx >> 2, ch = idx & 3;
        CP16(stg + r * 80 + ch * 16,           (const char*)(aHi + (size_t)r * aK) + ch * 16);
        CP16(stg + OFF_ALO + r * 80 + ch * 16, (const char*)(aLo + (size_t)r * aK) + ch * 16);
        CP16(stg + OFF_BHI + r * 80 + ch * 16, (const char*)(bHi + (size_t)r * bK) + ch * 16);
        CP16(stg + OFF_BLO + r * 80 + ch * 16, (const char*)(bLo + (size_t)r * bK) + ch * 16);
    }
}

// ---------------- compute one fused k32 chunk (3 split terms) --------------------
// 8 warps: wm in [0,4) (M32), wn in [0,2) (N64)
__device__ __forceinline__ void compute_chunk(uint32_t sa, float acc[2][8][4],
                                              int wm, int wn, int lane) {
#pragma unroll
    for (int kk = 0; kk < 2; ++kk) {
        uint32_t ahi[2][4], alo[2][4];
#pragma unroll
        for (int i = 0; i < 2; ++i) {
            const int row = wm * 32 + i * 16 + (lane & 15);
            const uint32_t off = row * 80 + kk * 32 + ((lane >> 4) << 4);
            ldsm4(ahi[i], sa + off);
            ldsm4(alo[i], sa + OFF_ALO + off);
        }
#pragma unroll
        for (int jp = 0; jp < 4; ++jp) {
            const int brow = wn * 64 + jp * 16 + ((lane & 7) | ((lane >> 4) << 3));
            const uint32_t boff = brow * 80 + kk * 32 + (((lane >> 3) & 1) << 4);
            uint32_t bh[4], bl[4];
            ldsm4(bh, sa + OFF_BHI + boff);
#pragma unroll
            for (int i = 0; i < 2; ++i) {
                mma16816(acc[i][jp * 2 + 0], ahi[i], &bh[0]);
                mma16816(acc[i][jp * 2 + 1], ahi[i], &bh[2]);
                mma16816(acc[i][jp * 2 + 0], alo[i], &bh[0]);
                mma16816(acc[i][jp * 2 + 1], alo[i], &bh[2]);
            }
            ldsm4(bl, sa + OFF_BLO + boff);
#pragma unroll
            for (int i = 0; i < 2; ++i) {
                mma16816(acc[i][jp * 2 + 0], ahi[i], &bl[0]);
                mma16816(acc[i][jp * 2 + 1], ahi[i], &bl[2]);
            }
        }
    }
}

// ---------------- weight repack ---------------------------------------------------
__global__ void conv_weights(const float* __restrict__ Wih, const float* __restrict__ Whh,
                             const float* __restrict__ Wmu, const float* __restrict__ Wsp) {
    int i = blockIdx.x * 256 + threadIdx.x;
    const int NG = 4096 * 1280;
    if (i < NG) {
        int r = i / 1280, k = i - r * 1280;
        int ny = r >> 7, w = r & 127;
        int wn = w >> 6, hcg = (w >> 5) & 1, gate = (w >> 3) & 3, h8 = w & 7;
        int hidden = ny * 32 + wn * 16 + hcg * 8 + h8;
        int o = gate * HID + hidden;
        float v = (k < FEAT) ? Wih[(size_t)o * FEAT + k] : Whh[(size_t)o * HID + (k - FEAT)];
        splt(v, g_Wg_hi[i], g_Wg_lo[i]);
    } else {
        int j = i - NG;
        if (j < 512 * 1024) {
            int r = j / 1024, k = j - r * 1024;
            int nb = r >> 7, w = r & 127;
            int wn = w >> 6, hcg = (w >> 4) & 3, head = (w >> 3) & 1, h8 = w & 7;
            int f = nb * 64 + wn * 32 + hcg * 8 + h8;
            float v = head ? Wsp[(size_t)f * HID + k] : Wmu[(size_t)f * HID + k];
            splt(v, g_Wo_hi[j], g_Wo_lo[j]);
        }
    }
}

// ---------------- encoder (SIMT fp32) ----------------------------------------------
__global__ void __launch_bounds__(256, 2) enc_kernel(const float* __restrict__ S,
                                                     const float* __restrict__ We,
                                                     const float* __restrict__ be) {
    __shared__ float As[16 * 65], Ws[16 * 33];
    const int tid = threadIdx.x, tx = tid & 15, ty = tid >> 4;
    const int m0 = blockIdx.x * 64, n0 = blockIdx.y * 32;
    float acc[8];
#pragma unroll
    for (int i = 0; i < 8; ++i) acc[i] = 0.f;
    const int rl = tid >> 2, kl = (tid & 3) * 4;
    for (int k0 = 0; k0 < SCENE; k0 += 16) {
        float4 v = *reinterpret_cast<const float4*>(&S[(size_t)(m0 + rl) * SCENE + k0 + kl]);
        As[(kl + 0) * 65 + rl] = v.x; As[(kl + 1) * 65 + rl] = v.y;
        As[(kl + 2) * 65 + rl] = v.z; As[(kl + 3) * 65 + rl] = v.w;
        if (tid < 128) {
            int c = tid >> 2, kc = (tid & 3) * 4;
            float4 w = *reinterpret_cast<const float4*>(&We[(size_t)(n0 + c) * SCENE + k0 + kc]);
            Ws[(kc + 0) * 33 + c] = w.x; Ws[(kc + 1) * 33 + c] = w.y;
            Ws[(kc + 2) * 33 + c] = w.z; Ws[(kc + 3) * 33 + c] = w.w;
        }
        __syncthreads();
#pragma unroll
        for (int k = 0; k < 16; ++k) {
            float a0 = As[k * 65 + ty * 4], a1 = As[k * 65 + ty * 4 + 1];
            float a2 = As[k * 65 + ty * 4 + 2], a3 = As[k * 65 + ty * 4 + 3];
            float w0 = Ws[k * 33 + tx * 2], w1 = Ws[k * 33 + tx * 2 + 1];
            acc[0] = fmaf(a0, w0, acc[0]); acc[1] = fmaf(a0, w1, acc[1]);
            acc[2] = fmaf(a1, w0, acc[2]); acc[3] = fmaf(a1, w1, acc[3]);
            acc[4] = fmaf(a2, w0, acc[4]); acc[5] = fmaf(a2, w1, acc[5]);
            acc[6] = fmaf(a3, w0, acc[6]); acc[7] = fmaf(a3, w1, acc[7]);
        }
        __syncthreads();
    }
#pragma unroll
    for (int c = 0; c < 2; ++c) {
        const int col = n0 + tx * 2 + c;
        const float b = be[col];
#pragma unroll
        for (int r = 0; r < 4; ++r) {
            const int row = m0 + ty * 4 + r;
            float v = acc[r * 2 + c] + b;
            v = 0.5f * v * (1.f + erff(v * 0.7071067811865476f));
            splt(v, g_x_hi[(size_t)row * FEAT + col], g_x_lo[(size_t)row * FEAT + col]);
        }
    }
}

// ---------------- gates GEMM + in-register LSTM cell --------------------------------
template <bool FIRST>
__global__ void __launch_bounds__(256, 2) gates_mma(int t, const float* __restrict__ bih,
                                                    const float* __restrict__ bhh) {
    extern __shared__ char sm[];
    const uint32_t smu = s2u(sm);
    const int tid = threadIdx.x, lane = tid & 31, wid = tid >> 5;
    const int wm = wid >> 1, wn = wid & 1;
    const int m0 = blockIdx.x * 128, ny = blockIdx.y;

    const bf16* hp_hi = (t & 1) ? g_hA_hi : g_hB_hi;
    const bf16* hp_lo = (t & 1) ? g_hA_lo : g_hB_lo;
    bf16* ho_hi = (t & 1) ? g_hB_hi : g_hA_hi;
    bf16* ho_lo = (t & 1) ? g_hB_lo : g_hA_lo;

    float* bs = reinterpret_cast<float*>(sm + OFF_BIAS);
    if (tid < 128) {
        int wn2 = tid >> 6, hcg = (tid >> 5) & 1, gate = (tid >> 3) & 3, h8 = tid & 7;
        int hidden = ny * 32 + wn2 * 16 + hcg * 8 + h8;
        bs[tid] = bih[gate * HID + hidden] + bhh[gate * HID + hidden];
    }

    const int NC = FIRST ? 8 : 40;
    float acc[2][8][4];
#pragma unroll
    for (int i = 0; i < 2; ++i)
#pragma unroll
        for (int j = 0; j < 8; ++j)
#pragma unroll
            for (int e = 0; e < 4; ++e) acc[i][j][e] = 0.f;

    auto issue_load = [&](int cs) {
        const int kc = cs * 32;
        const bf16 *aH, *aL; int aK;
        if (FIRST || kc < 256) {
            aH = g_x_hi + (size_t)m0 * FEAT + kc;
            aL = g_x_lo + (size_t)m0 * FEAT + kc; aK = FEAT;
        } else {
            aH = hp_hi + (size_t)m0 * HID + (kc - 256);
            aL = hp_lo + (size_t)m0 * HID + (kc - 256); aK = HID;
        }
        const size_t bo = (size_t)(ny * 128) * 1280 + kc;
        load_chunk(smu + (cs & 1) * STG, aH, aL, aK, g_Wg_hi + bo, g_Wg_lo + bo, 1280, tid);
        CPCOMMIT();
    };

    issue_load(0); issue_load(1);
    for (int cs = 0; cs < NC; ++cs) {
        CPWAIT1();
        __syncthreads();
        compute_chunk(smu + (cs & 1) * STG, acc, wm, wn, lane);
        __syncthreads();
        if (cs + 2 < NC) issue_load(cs + 2); else CPCOMMIT();
    }

    // in-register LSTM cell epilogue: acc col j = hcg*4 + gate
    const int lane4 = lane >> 2, lq = lane & 3;
#pragma unroll
    for (int i = 0; i < 2; ++i)
#pragma unroll
        for (int rp = 0; rp < 2; ++rp) {
            const int row = m0 + wm * 32 + i * 16 + lane4 + rp * 8;
#pragma unroll
            for (int hcg = 0; hcg < 2; ++hcg) {
                const int h8b = lq * 2;
                const int hidden = ny * 32 + wn * 16 + hcg * 8 + h8b;
                const size_t base = (size_t)row * HID + hidden;
                const int bb = wn * 64 + hcg * 32 + h8b;
                float2 cold = make_float2(0.f, 0.f);
                if (!FIRST) cold = *reinterpret_cast<const float2*>(&g_c[base]);
                float cn[2];
                union { bf16 b[2]; uint32_t u; } Hh, Hl;
#pragma unroll
                for (int eb = 0; eb < 2; ++eb) {
                    const int e = rp * 2 + eb;
                    const float gi = acc[i][hcg * 4 + 0][e] + bs[bb + 0 + eb];
                    const float gf = acc[i][hcg * 4 + 1][e] + bs[bb + 8 + eb];
                    const float gg = acc[i][hcg * 4 + 2][e] + bs[bb + 16 + eb];
                    const float go = acc[i][hcg * 4 + 3][e] + bs[bb + 24 + eb];
                    const float cp = FIRST ? 0.f : (eb ? cold.y : cold.x);
                    const float c2 = sig_(gf) * cp + sig_(gi) * tanh_(gg);
                    cn[eb] = c2;
                    splt(sig_(go) * tanh_(c2), Hh.b[eb], Hl.b[eb]);
                }
                *reinterpret_cast<float2*>(&g_c[base]) = make_float2(cn[0], cn[1]);
                *reinterpret_cast<uint32_t*>(&ho_hi[base]) = Hh.u;
                *reinterpret_cast<uint32_t*>(&ho_lo[base]) = Hl.u;
            }
        }
}

// ---------------- heads GEMM: mu | softplus sigma | z --------------------------------
__global__ void __launch_bounds__(256, 2) heads_mma(int t, const float* __restrict__ bmu,
                                                    const float* __restrict__ bsp,
                                                    const float* __restrict__ eps,
                                                    float* __restrict__ zs,
                                                    float* __restrict__ mus,
                                                    float* __restrict__ sgs) {
    extern __shared__ char sm[];
    const uint32_t smu = s2u(sm);
    const int tid = threadIdx.x, lane = tid & 31, wid = tid >> 5;
    const int wm = wid >> 1, wn = wid & 1;
    const int m0 = blockIdx.x * 128, nb = blockIdx.y;

    const bf16* hc_hi = (t & 1) ? g_hB_hi : g_hA_hi;
    const bf16* hc_lo = (t & 1) ? g_hB_lo : g_hA_lo;

    float* bs = reinterpret_cast<float*>(sm + OFF_BIAS);
    if (tid < 128) {
        int wn2 = tid >> 6, hcg = (tid >> 4) & 3, head = (tid >> 3) & 1, h8 = tid & 7;
        int f = nb * 64 + wn2 * 32 + hcg * 8 + h8;
        bs[tid] = head ? bsp[f] : bmu[f];
    }

    const int NC = 32;
    float acc[2][8][4];
#pragma unroll
    for (int i = 0; i < 2; ++i)
#pragma unroll
        for (int j = 0; j < 8; ++j)
#pragma unroll
            for (int e = 0; e < 4; ++e) acc[i][j][e] = 0.f;

    auto issue_load = [&](int cs) {
        const int kc = cs * 32;
        const bf16* aH = hc_hi + (size_t)m0 * HID + kc;
        const bf16* aL = hc_lo + (size_t)m0 * HID + kc;
        const size_t bo = (size_t)(nb * 128) * 1024 + kc;
        load_chunk(smu + (cs & 1) * STG, aH, aL, HID, g_Wo_hi + bo, g_Wo_lo + bo, 1024, tid);
        CPCOMMIT();
    };

    issue_load(0); issue_load(1);
    for (int cs = 0; cs < NC; ++cs) {
        CPWAIT1();
        __syncthreads();
        compute_chunk(smu + (cs & 1) * STG, acc, wm, wn, lane);
        __syncthreads();
        if (cs + 2 < NC) issue_load(cs + 2); else CPCOMMIT();
    }

    // in-register heads epilogue: acc col j = hcg*2 + head
    const int lane4 = lane >> 2, lq = lane & 3;
#pragma unroll
    for (int i = 0; i < 2; ++i)
#pragma unroll
        for (int rp = 0; rp < 2; ++rp) {
            const int row = m0 + wm * 32 + i * 16 + lane4 + rp * 8;
#pragma unroll
            for (int hcg = 0; hcg < 4; ++hcg) {
                const int h8b = lq * 2;
                const int f = nb * 64 + wn * 32 + hcg * 8 + h8b;
                const size_t o = (size_t)t * B_SZ * FEAT + (size_t)row * FEAT + f;
                const size_t xb = (size_t)row * FEAT + f;
                const int bb = wn * 64 + hcg * 16 + h8b;
                const float2 ev = *reinterpret_cast<const float2*>(&eps[o]);
                float zv[2], mv[2], sv[2];
                union { bf16 b[2]; uint32_t u; } Zh, Zl;
#pragma unroll
                for (int eb = 0; eb < 2; ++eb) {
                    const int e = rp * 2 + eb;
                    const float mu = acc[i][hcg * 2 + 0][e] + bs[bb + 0 + eb];
                    const float sg = sp_(acc[i][hcg * 2 + 1][e] + bs[bb + 8 + eb]);
                    const float z = mu + sg * (eb ? ev.y : ev.x);
                    mv[eb] = mu; sv[eb] = sg; zv[eb] = z;
                    splt(z, Zh.b[eb], Zl.b[eb]);
                }
                *reinterpret_cast<float2*>(&zs[o])  = make_float2(zv[0], zv[1]);
                *reinterpret_cast<float2*>(&mus[o]) = make_float2(mv[0], mv[1]);
                *reinterpret_cast<float2*>(&sgs[o]) = make_float2(sv[0], sv[1]);
                *reinterpret_cast<uint32_t*>(&g_x_hi[xb]) = Zh.u;
                *reinterpret_cast<uint32_t*>(&g_x_lo[xb]) = Zl.u;
            }
        }
}

// ---------------- launch --------------------------------------------------------------
extern "C" void kernel_launch(void* const* d_in, const int* in_sizes, int n_in,
                              void* d_out, int out_size) {
    (void)in_sizes; (void)n_in; (void)out_size;
    const float* S   = (const float*)d_in[0];
    const float* eps = (const float*)d_in[1];
    const float* We  = (const float*)d_in[3];
    const float* be  = (const float*)d_in[4];
    const float* Wih = (const float*)d_in[5];
    const float* Whh = (const float*)d_in[6];
    const float* bih = (const float*)d_in[7];
    const float* bhh = (const float*)d_in[8];
    const float* Wmu = (const float*)d_in[9];
    const float* bmu = (const float*)d_in[10];
    const float* Wsp = (const float*)d_in[11];
    const float* bsp = (const float*)d_in[12];

    float* out = (float*)d_out;
    const size_t slab = (size_t)NSLOTS * B_SZ * FEAT;
    float *zs = out, *mus = out + slab, *sgs = out + 2 * slab;

    static bool attr_done = false;
    if (!attr_done) {
        cudaFuncSetAttribute(gates_mma<true>,  cudaFuncAttributeMaxDynamicSharedMemorySize, SMEM_T);
        cudaFuncSetAttribute(gates_mma<false>, cudaFuncAttributeMaxDynamicSharedMemorySize, SMEM_T);
        cudaFuncSetAttribute(heads_mma,        cudaFuncAttributeMaxDynamicSharedMemorySize, SMEM_T);
        attr_done = true;
    }

    conv_weights<<<22528, 256>>>(Wih, Whh, Wmu, Wsp);
    enc_kernel<<<dim3(B_SZ / 64, FEAT / 32), 256>>>(S, We, be);

    for (int t = 0; t < NSLOTS; ++t) {
        if (t == 0)
            gates_mma<true><<<dim3(B_SZ / 128, 32), 256, SMEM_T>>>(t, bih, bhh);
        else
            gates_mma<false><<<dim3(B_SZ / 128, 32), 256, SMEM_T>>>(t, bih, bhh);
        heads_mma<<<dim3(B_SZ / 128, 4), 256, SMEM_T>>>(t, bmu, bsp, eps, zs, mus, sgs);
    }
}